// round 1
// baseline (speedup 1.0000x reference)
#include <cuda_runtime.h>
#include <math.h>

// Problem constants
#define Bsz 256
#define Tsz 512
#define Esz 512
#define Hsz 1024
#define Csz 128
#define NG  4096   // 4*H
#define KHC 1152   // H + C

// ---------------- device scratch (static globals: allocation-free) ----------
// Per-gate input pre-activations G = x@W_ih^T + b_ih + b_hh   (512 MB each)
__device__ float d_Gi[(size_t)Bsz * Tsz * Hsz];
__device__ float d_Gf[(size_t)Bsz * Tsz * Hsz];
__device__ float d_Gg[(size_t)Bsz * Tsz * Hsz];
__device__ float d_Go[(size_t)Bsz * Tsz * Hsz];
// Gate-interleaved recurrent weights: Wr[(j*4+g)*H + k] = W_hh[(g*H+j)*H + k]
__device__ float d_Wr[(size_t)NG * Hsz];
// Double-buffered hidden state + cell state
__device__ float d_hA[Bsz * Hsz];
__device__ float d_hB[Bsz * Hsz];
__device__ float d_cst[Bsz * Hsz];
// All hidden states over time (feeds final linear)     (512 MB)
__device__ float d_Hout[(size_t)Bsz * Tsz * Hsz];
// EMA-blended categories                               (64 MB)
__device__ float d_ceff[(size_t)Bsz * Tsz * Csz];

// ---------------- helpers ----------------------------------------------------
__device__ __forceinline__ float sigmoidf_(float x) {
    return 1.0f / (1.0f + expf(-x));
}

// ---------------- init / preprocessing --------------------------------------
__global__ void zero_state_kernel() {
    int i = blockIdx.x * blockDim.x + threadIdx.x;
    if (i < Bsz * Hsz) { d_hA[i] = 0.0f; d_cst[i] = 0.0f; }
}

__global__ void reorder_whh_kernel(const float* __restrict__ W_hh) {
    int idx = blockIdx.x * blockDim.x + threadIdx.x;   // over NG*Hsz
    if (idx >= NG * Hsz) return;
    int k  = idx & (Hsz - 1);
    int np = idx >> 10;          // j*4+g
    int j  = np >> 2;
    int g  = np & 3;
    d_Wr[idx] = W_hh[((size_t)(g * Hsz + j)) * Hsz + k];
}

// cate EMA scan: eff[0]=cate[0]; eff[t]=0.9*eff[t-1]+0.1*cate[t]
__global__ void ema_kernel(const float* __restrict__ cate) {
    int b = blockIdx.x;
    int c = threadIdx.x;          // Csz threads
    size_t base = (size_t)b * Tsz * Csz + c;
    float prev = 0.0f;
    for (int t = 0; t < Tsz; t++) {
        float v = cate[base + (size_t)t * Csz];
        float eff = (t == 0) ? v : fmaf(0.9f, prev, 0.1f * v);
        d_ceff[base + (size_t)t * Csz] = eff;
        prev = eff;
    }
}

// ---------------- big input GEMM: G = x @ W_ih^T + (b_ih + b_hh) ------------
// A = x [131072, 512] row-major, B = W_ih [4096, 512] row-major (NT GEMM)
// BM=128, BN=128, BK=8, TM=TN=8, 256 threads
__global__ void __launch_bounds__(256)
gemm_input_kernel(const float* __restrict__ x,
                  const float* __restrict__ W_ih,
                  const float* __restrict__ b_ih,
                  const float* __restrict__ b_hh) {
    __shared__ float As[8][132];
    __shared__ float Bs[8][132];

    const int tid = threadIdx.x;
    const int tx = tid & 15, ty = tid >> 4;
    const int m0 = blockIdx.y * 128;
    const int n0 = blockIdx.x * 128;

    const int lrow = tid >> 1;         // 0..127
    const int lk   = (tid & 1) * 4;    // 0 or 4
    const float* Aptr = x    + (size_t)(m0 + lrow) * Esz + lk;
    const float* Bptr = W_ih + (size_t)(n0 + lrow) * Esz + lk;

    float acc[8][8];
#pragma unroll
    for (int i = 0; i < 8; i++)
#pragma unroll
        for (int j = 0; j < 8; j++) acc[i][j] = 0.0f;

    for (int k0 = 0; k0 < Esz; k0 += 8) {
        float4 av = *(const float4*)(Aptr + k0);
        float4 bv = *(const float4*)(Bptr + k0);
        As[lk + 0][lrow] = av.x; As[lk + 1][lrow] = av.y;
        As[lk + 2][lrow] = av.z; As[lk + 3][lrow] = av.w;
        Bs[lk + 0][lrow] = bv.x; Bs[lk + 1][lrow] = bv.y;
        Bs[lk + 2][lrow] = bv.z; Bs[lk + 3][lrow] = bv.w;
        __syncthreads();
#pragma unroll
        for (int kk = 0; kk < 8; kk++) {
            float a[8], b[8];
            *(float4*)&a[0] = *(const float4*)&As[kk][ty * 8];
            *(float4*)&a[4] = *(const float4*)&As[kk][ty * 8 + 4];
            *(float4*)&b[0] = *(const float4*)&Bs[kk][tx * 8];
            *(float4*)&b[4] = *(const float4*)&Bs[kk][tx * 8 + 4];
#pragma unroll
            for (int i = 0; i < 8; i++)
#pragma unroll
                for (int j = 0; j < 8; j++)
                    acc[i][j] = fmaf(a[i], b[j], acc[i][j]);
        }
        __syncthreads();
    }

    // epilogue: per-gate array (a 128-col block never straddles a gate)
    const int gate = n0 >> 10;
    float* Gp = (gate == 0) ? d_Gi : (gate == 1) ? d_Gf : (gate == 2) ? d_Gg : d_Go;
    const int jb = (n0 & (Hsz - 1)) + tx * 8;

    float bias[8];
#pragma unroll
    for (int j = 0; j < 8; j++) {
        int n = n0 + tx * 8 + j;
        bias[j] = b_ih[n] + b_hh[n];
    }
#pragma unroll
    for (int i = 0; i < 8; i++) {
        size_t r = (size_t)(m0 + ty * 8 + i);
        float4 v0, v1;
        v0.x = acc[i][0] + bias[0]; v0.y = acc[i][1] + bias[1];
        v0.z = acc[i][2] + bias[2]; v0.w = acc[i][3] + bias[3];
        v1.x = acc[i][4] + bias[4]; v1.y = acc[i][5] + bias[5];
        v1.z = acc[i][6] + bias[6]; v1.w = acc[i][7] + bias[7];
        *(float4*)(Gp + r * Hsz + jb)     = v0;
        *(float4*)(Gp + r * Hsz + jb + 4) = v1;
    }
}

// ---------------- per-timestep recurrent GEMM + fused LSTM cell --------------
// gates = G[:,t,:] + h @ Wr^T ; cell update fused in epilogue.
// A = h [256,1024], B = Wr [4096,1024] (NT). BM=64, BN=64, BK=16, TM=TN=4.
__global__ void __launch_bounds__(256)
gemm_step_kernel(int t, int parity) {
    const float* hin = parity ? d_hB : d_hA;
    float*      hout = parity ? d_hA : d_hB;

    __shared__ float As[16][68];
    __shared__ float Bs[16][68];

    const int tid = threadIdx.x;
    const int tx = tid & 15, ty = tid >> 4;
    const int n0 = blockIdx.x * 64;
    const int m0 = blockIdx.y * 64;

    const int lrow = tid >> 2;        // 0..63
    const int lk   = (tid & 3) * 4;   // 0,4,8,12
    const float* Aptr = hin  + (size_t)(m0 + lrow) * Hsz + lk;
    const float* Bptr = d_Wr + (size_t)(n0 + lrow) * Hsz + lk;

    float acc[4][4];
#pragma unroll
    for (int i = 0; i < 4; i++)
#pragma unroll
        for (int j = 0; j < 4; j++) acc[i][j] = 0.0f;

    for (int k0 = 0; k0 < Hsz; k0 += 16) {
        float4 av = *(const float4*)(Aptr + k0);
        float4 bv = *(const float4*)(Bptr + k0);
        As[lk + 0][lrow] = av.x; As[lk + 1][lrow] = av.y;
        As[lk + 2][lrow] = av.z; As[lk + 3][lrow] = av.w;
        Bs[lk + 0][lrow] = bv.x; Bs[lk + 1][lrow] = bv.y;
        Bs[lk + 2][lrow] = bv.z; Bs[lk + 3][lrow] = bv.w;
        __syncthreads();
#pragma unroll
        for (int kk = 0; kk < 16; kk++) {
            float4 a = *(const float4*)&As[kk][ty * 4];
            float4 b = *(const float4*)&Bs[kk][tx * 4];
            acc[0][0] = fmaf(a.x, b.x, acc[0][0]); acc[0][1] = fmaf(a.x, b.y, acc[0][1]);
            acc[0][2] = fmaf(a.x, b.z, acc[0][2]); acc[0][3] = fmaf(a.x, b.w, acc[0][3]);
            acc[1][0] = fmaf(a.y, b.x, acc[1][0]); acc[1][1] = fmaf(a.y, b.y, acc[1][1]);
            acc[1][2] = fmaf(a.y, b.z, acc[1][2]); acc[1][3] = fmaf(a.y, b.w, acc[1][3]);
            acc[2][0] = fmaf(a.z, b.x, acc[2][0]); acc[2][1] = fmaf(a.z, b.y, acc[2][1]);
            acc[2][2] = fmaf(a.z, b.z, acc[2][2]); acc[2][3] = fmaf(a.z, b.w, acc[2][3]);
            acc[3][0] = fmaf(a.w, b.x, acc[3][0]); acc[3][1] = fmaf(a.w, b.y, acc[3][1]);
            acc[3][2] = fmaf(a.w, b.z, acc[3][2]); acc[3][3] = fmaf(a.w, b.w, acc[3][3]);
        }
        __syncthreads();
    }

    // fused LSTM cell: this thread owns hidden unit j for 4 batch rows
    const int j = (n0 >> 2) + tx;
#pragma unroll
    for (int i = 0; i < 4; i++) {
        int b = m0 + ty * 4 + i;
        size_t idx = ((size_t)b * Tsz + t) * Hsz + j;
        float pi = acc[i][0] + d_Gi[idx];
        float pf = acc[i][1] + d_Gf[idx];
        float pg = acc[i][2] + d_Gg[idx];
        float po = acc[i][3] + d_Go[idx];
        float ig = sigmoidf_(pi);
        float fg = sigmoidf_(pf);
        float gg = tanhf(pg);
        float og = sigmoidf_(po);
        int sidx = b * Hsz + j;
        float cn = fmaf(fg, d_cst[sidx], ig * gg);
        d_cst[sidx] = cn;
        float hn = og * tanhf(cn);
        hout[sidx]  = hn;
        d_Hout[idx] = hn;
    }
}

// ---------------- final linear: out = mask(concat(h,ceff)) @ W_lin^T + b_lin -
// A = concat(Hout, ceff) [131072, 1152], B = W_lin [512, 1152] (NT)
// BM=128, BN=64, BK=16, TM=8, TN=4, 256 threads
__global__ void __launch_bounds__(256)
gemm_final_kernel(const float* __restrict__ W_lin,
                  const float* __restrict__ b_lin,
                  const int*   __restrict__ seq_lens,
                  float*       __restrict__ out) {
    __shared__ float As[16][132];
    __shared__ float Bs[16][68];

    const int tid = threadIdx.x;
    const int tx = tid & 15, ty = tid >> 4;
    const int m0 = blockIdx.y * 128;
    const int n0 = blockIdx.x * 64;

    const int lrowA = tid >> 1;        // 0..127
    const int lkA   = (tid & 1) * 8;   // 0 or 8
    const int lrowB = tid >> 2;        // 0..63
    const int lkB   = (tid & 3) * 4;   // 0,4,8,12

    float acc[8][4];
#pragma unroll
    for (int i = 0; i < 8; i++)
#pragma unroll
        for (int j = 0; j < 4; j++) acc[i][j] = 0.0f;

    for (int k0 = 0; k0 < KHC; k0 += 16) {
        // A tile: first 1024 cols from Hout, rest from ceff (tiles never straddle)
        const float* Abase;
        if (k0 < Hsz)
            Abase = d_Hout + (size_t)(m0 + lrowA) * Hsz + k0 + lkA;
        else
            Abase = d_ceff + (size_t)(m0 + lrowA) * Csz + (k0 - Hsz) + lkA;
        float4 a0 = *(const float4*)(Abase);
        float4 a1 = *(const float4*)(Abase + 4);
        As[lkA + 0][lrowA] = a0.x; As[lkA + 1][lrowA] = a0.y;
        As[lkA + 2][lrowA] = a0.z; As[lkA + 3][lrowA] = a0.w;
        As[lkA + 4][lrowA] = a1.x; As[lkA + 5][lrowA] = a1.y;
        As[lkA + 6][lrowA] = a1.z; As[lkA + 7][lrowA] = a1.w;

        float4 bvv = *(const float4*)(W_lin + (size_t)(n0 + lrowB) * KHC + k0 + lkB);
        Bs[lkB + 0][lrowB] = bvv.x; Bs[lkB + 1][lrowB] = bvv.y;
        Bs[lkB + 2][lrowB] = bvv.z; Bs[lkB + 3][lrowB] = bvv.w;
        __syncthreads();
#pragma unroll
        for (int kk = 0; kk < 16; kk++) {
            float a[8], b[4];
            *(float4*)&a[0] = *(const float4*)&As[kk][ty * 8];
            *(float4*)&a[4] = *(const float4*)&As[kk][ty * 8 + 4];
            *(float4*)&b[0] = *(const float4*)&Bs[kk][tx * 4];
#pragma unroll
            for (int i = 0; i < 8; i++)
#pragma unroll
                for (int j = 0; j < 4; j++)
                    acc[i][j] = fmaf(a[i], b[j], acc[i][j]);
        }
        __syncthreads();
    }

    const int e0 = n0 + tx * 4;
    float bl0 = b_lin[e0], bl1 = b_lin[e0 + 1], bl2 = b_lin[e0 + 2], bl3 = b_lin[e0 + 3];
#pragma unroll
    for (int i = 0; i < 8; i++) {
        size_t r = (size_t)(m0 + ty * 8 + i);
        int b = (int)(r >> 9);          // T = 512
        int t = (int)(r & 511);
        bool act = t < seq_lens[b];
        float4 v;
        v.x = bl0 + (act ? acc[i][0] : 0.0f);
        v.y = bl1 + (act ? acc[i][1] : 0.0f);
        v.z = bl2 + (act ? acc[i][2] : 0.0f);
        v.w = bl3 + (act ? acc[i][3] : 0.0f);
        *(float4*)(out + r * Esz + e0) = v;
    }
}

// ---------------- launch ------------------------------------------------------
extern "C" void kernel_launch(void* const* d_in, const int* in_sizes, int n_in,
                              void* d_out, int out_size) {
    const float* x     = (const float*)d_in[0];
    const float* cate  = (const float*)d_in[1];
    const int*   seq   = (const int*)  d_in[2];
    const float* W_ih  = (const float*)d_in[3];
    const float* W_hh  = (const float*)d_in[4];
    const float* b_ih  = (const float*)d_in[5];
    const float* b_hh  = (const float*)d_in[6];
    const float* W_lin = (const float*)d_in[7];
    const float* b_lin = (const float*)d_in[8];
    float* out = (float*)d_out;

    zero_state_kernel<<<(Bsz * Hsz + 255) / 256, 256>>>();
    reorder_whh_kernel<<<(NG * Hsz + 255) / 256, 256>>>(W_hh);
    ema_kernel<<<Bsz, Csz>>>(cate);

    // G = x @ W_ih^T + biases : grid (N/128, M/128) = (32, 1024)
    gemm_input_kernel<<<dim3(NG / 128, (Bsz * Tsz) / 128), 256>>>(x, W_ih, b_ih, b_hh);

    // recurrence: 512 dependent steps, h double-buffered
    for (int t = 0; t < Tsz; t++)
        gemm_step_kernel<<<dim3(NG / 64, Bsz / 64), 256>>>(t, t & 1);

    // final linear: grid (E/64, M/128) = (8, 1024)
    gemm_final_kernel<<<dim3(Esz / 64, (Bsz * Tsz) / 128), 256>>>(W_lin, b_lin, seq, out);
}